// round 14
// baseline (speedup 1.0000x reference)
#include <cuda_runtime.h>
#include <cuda_bf16.h>
#include <math.h>
#include <stdint.h>

// ---------------------------------------------------------------------------
// DGCNN forward, B=8, C=3, N=2048, K=20
// knn+conv1 fused; mma.sync bf16-split convs (NT=64, SW128-swizzled smem,
// 4 blocks/SM); loader-fused BN+LReLU+split; k-max fused into epilogues.
// ---------------------------------------------------------------------------

#define B_      8
#define N_      2048
#define KNN_    20
#define ROWS_   (B_ * N_)                 // 16384
#define M1_     (ROWS_ * KNN_)            // 327680

#define W2_OFF  0
#define W3_OFF  4096
#define W4_OFF  12288
#define W5_OFF  45056
#define W_TOTAL 569344

// Static device scratch
__device__ float          g_ya[M1_ * 128];          // y1 (64ch), y3 (128ch)
__device__ float          g_yb[M1_ * 64];           // y2 (64ch)
__device__ float          g_y5[ROWS_ * 1024];
__device__ unsigned int   g_ymax[ROWS_ * 512];
__device__ __nv_bfloat16  g_cathi[ROWS_ * 512];
__device__ __nv_bfloat16  g_catlo[ROWS_ * 512];
__device__ __nv_bfloat16  g_whi[W_TOTAL];
__device__ __nv_bfloat16  g_wlo[W_TOTAL];
__device__ float  g_sum[1536];
__device__ float  g_sq [1536];
__device__ float  g_scale[1536];
__device__ float  g_bias [1536];

// ---------------------------------------------------------------------------
__device__ __forceinline__ uint32_t smem_to_u32(const void* p) {
    uint32_t a;
    asm("{ .reg .u64 t; cvta.to.shared.u64 t, %1; cvt.u32.u64 %0, t; }" : "=r"(a) : "l"(p));
    return a;
}
__device__ __forceinline__ void ldsm_x4(uint32_t addr, uint32_t r[4]) {
    asm volatile("ldmatrix.sync.aligned.m8n8.x4.shared.b16 {%0,%1,%2,%3}, [%4];"
                 : "=r"(r[0]), "=r"(r[1]), "=r"(r[2]), "=r"(r[3]) : "r"(addr));
}
__device__ __forceinline__ void mma_bf16(float c[4], const uint32_t a[4], const uint32_t b[2]) {
    asm volatile("mma.sync.aligned.m16n8k16.row.col.f32.bf16.bf16.f32 "
                 "{%0,%1,%2,%3}, {%4,%5,%6,%7}, {%8,%9}, {%0,%1,%2,%3};"
                 : "+f"(c[0]), "+f"(c[1]), "+f"(c[2]), "+f"(c[3])
                 : "r"(a[0]), "r"(a[1]), "r"(a[2]), "r"(a[3]), "r"(b[0]), "r"(b[1]));
}
__device__ __forceinline__ void cpa16(uint32_t saddr, const void* g) {
    asm volatile("cp.async.cg.shared.global [%0], [%1], 16;" :: "r"(saddr), "l"(g));
}
__device__ __forceinline__ unsigned int enc_f(float f) {
    unsigned int b = __float_as_uint(f);
    return b ^ ((unsigned int)((int)b >> 31) | 0x80000000u);
}
__device__ __forceinline__ float dec_f(unsigned int e) {
    unsigned int b = (e & 0x80000000u) ? (e ^ 0x80000000u) : ~e;
    return __uint_as_float(b);
}
__device__ __forceinline__ uint32_t pack_bf2(float v0, float v1, uint32_t& lo) {
    __nv_bfloat16 h0 = __float2bfloat16_rn(v0);
    __nv_bfloat16 h1 = __float2bfloat16_rn(v1);
    __nv_bfloat16 l0 = __float2bfloat16_rn(v0 - __bfloat162float(h0));
    __nv_bfloat16 l1 = __float2bfloat16_rn(v1 - __bfloat162float(h1));
    lo = (uint32_t)__bfloat16_as_ushort(l0) | ((uint32_t)__bfloat16_as_ushort(l1) << 16);
    return (uint32_t)__bfloat16_as_ushort(h0) | ((uint32_t)__bfloat16_as_ushort(h1) << 16);
}
// SW128 swizzle on 128B rows: 16B-granule u, row m -> granule u ^ (m & 7)
__device__ __forceinline__ uint32_t swz(int m, int u) {
    return (uint32_t)(m * 128 + ((u ^ (m & 7)) << 4));
}

// ---------------------------------------------------------------------------
__global__ void init_stats_kernel() {
    int t = blockIdx.x * 256 + threadIdx.x;
    if (t < 1536) { g_sum[t] = 0.0f; g_sq[t] = 0.0f; }
}

// ---------------------------------------------------------------------------
// kNN + edge features + FUSED conv1 (6->64) + stats1 + ymax1 (+ W split etc).
// ---------------------------------------------------------------------------
__global__ void __launch_bounds__(256) knn_conv1_kernel(
    const float* __restrict__ x,  const float* __restrict__ W1,
    const float* __restrict__ W2, const float* __restrict__ W3,
    const float* __restrict__ W4, const float* __restrict__ W5)
{
    extern __shared__ float ksm[];
    float* xs0  = ksm;
    float* xs1  = ksm + 2048;
    float* xs2  = ksm + 4096;
    float* dist = ksm + 6144;
    __shared__ int   selw[8][KNN_];
    __shared__ float W1s[384];
    __shared__ float bsum[64], bsq[64];

    const int b   = blockIdx.y;
    const int tid = threadIdx.x;
    const int w   = tid >> 5, lane = tid & 31;
    const int il  = blockIdx.x * 8 + w;
    const float* xb = x + (size_t)b * 3 * N_;

    const int fb  = blockIdx.y * gridDim.x + blockIdx.x;
    const int gt  = fb * 256 + tid;
    const int NTH = gridDim.x * gridDim.y * 256;
    for (int t = gt; t < W_TOTAL; t += NTH) {
        const float* src; int idx;
        if      (t < W3_OFF) { src = W2; idx = t; }
        else if (t < W4_OFF) { src = W3; idx = t - W3_OFF; }
        else if (t < W5_OFF) { src = W4; idx = t - W4_OFF; }
        else                 { src = W5; idx = t - W5_OFF; }
        float v = src[idx];
        __nv_bfloat16 h = __float2bfloat16_rn(v);
        g_whi[t] = h;
        g_wlo[t] = __float2bfloat16_rn(v - __bfloat162float(h));
    }
    const unsigned int NEG = enc_f(-3.4e38f);
    for (int idx = gt; idx < ROWS_ * 448; idx += NTH) {
        int r = idx / 448, c = idx - r * 448;
        g_ymax[(size_t)r * 512 + 64 + c] = NEG;
    }
    for (int t = tid; t < 384; t += 256) W1s[t] = W1[t];
    if (tid < 64) { bsum[tid] = 0.0f; bsq[tid] = 0.0f; }

    for (int j = tid; j < N_; j += 256) {
        xs0[j] = xb[j];
        xs1[j] = xb[N_ + j];
        xs2[j] = xb[2 * N_ + j];
    }
    __syncthreads();

    const float p0 = xs0[il], p1 = xs1[il], p2 = xs2[il];
    const float xxi = p0 * p0 + p1 * p1 + p2 * p2;
    float* dw = dist + w * 2048;

    for (int j = lane; j < N_; j += 32) {
        float q0 = xs0[j], q1 = xs1[j], q2 = xs2[j];
        float inner = p0 * q0 + p1 * q1 + p2 * q2;
        float xxj = q0 * q0 + q1 * q1 + q2 * q2;
        dw[j] = 2.0f * inner - xxi - xxj;
    }
    __syncwarp();

    for (int t = 0; t < KNN_; t++) {
        float v = -3.0e38f; int bj = N_;
        #pragma unroll 8
        for (int j = lane; j < N_; j += 32) {
            float d = dw[j];
            if (d > v || (d == v && j < bj)) { v = d; bj = j; }
        }
        #pragma unroll
        for (int s = 16; s > 0; s >>= 1) {
            float ov = __shfl_down_sync(0xffffffffu, v, s);
            int   oj = __shfl_down_sync(0xffffffffu, bj, s);
            if (ov > v || (ov == v && oj < bj)) { v = ov; bj = oj; }
        }
        bj = __shfl_sync(0xffffffffu, bj, 0);
        if (lane == 0) { selw[w][t] = bj; dw[bj] = -3.3e38f; }
        __syncwarp();
    }
    __syncwarp();

    const int p = b * N_ + il;
    float w0[6], w1[6];
    #pragma unroll
    for (int c = 0; c < 6; c++) {
        w0[c] = W1s[(2 * lane) * 6 + c];
        w1[c] = W1s[(2 * lane + 1) * 6 + c];
    }
    float s0 = 0.0f, s1 = 0.0f, q0 = 0.0f, q1 = 0.0f;
    float mx0 = -3.4e38f, mx1 = -3.4e38f;
    #pragma unroll 4
    for (int k = 0; k < KNN_; k++) {
        int j = selw[w][k];
        float e0 = xs0[j] - p0, e1 = xs1[j] - p1, e2 = xs2[j] - p2;
        float y0 = e0 * w0[0];
        y0 = fmaf(e1, w0[1], y0); y0 = fmaf(e2, w0[2], y0);
        y0 = fmaf(p0, w0[3], y0); y0 = fmaf(p1, w0[4], y0); y0 = fmaf(p2, w0[5], y0);
        float y1 = e0 * w1[0];
        y1 = fmaf(e1, w1[1], y1); y1 = fmaf(e2, w1[2], y1);
        y1 = fmaf(p0, w1[3], y1); y1 = fmaf(p1, w1[4], y1); y1 = fmaf(p2, w1[5], y1);
        *(float2*)&g_ya[((size_t)p * KNN_ + k) * 64 + 2 * lane] = make_float2(y0, y1);
        mx0 = fmaxf(mx0, y0); mx1 = fmaxf(mx1, y1);
        s0 += y0; s1 += y1;
        q0 = fmaf(y0, y0, q0); q1 = fmaf(y1, y1, q1);
    }
    g_ymax[(size_t)p * 512 + 2 * lane]     = enc_f(mx0);
    g_ymax[(size_t)p * 512 + 2 * lane + 1] = enc_f(mx1);
    atomicAdd(&bsum[2 * lane], s0);
    atomicAdd(&bsum[2 * lane + 1], s1);
    atomicAdd(&bsq [2 * lane], q0);
    atomicAdd(&bsq [2 * lane + 1], q1);
    __syncthreads();
    if (tid < 64) {
        atomicAdd(&g_sum[tid], bsum[tid]);
        atomicAdd(&g_sq [tid], bsq[tid]);
    }
}

// ---------------------------------------------------------------------------
// mma.sync bf16-split GEMM. NT=64 (NFRAG=4), SW128 swizzled smem, 4 blocks/SM.
// ---------------------------------------------------------------------------
template<int CIN, bool CONVA, bool WRITE_Y, bool DO_MAX>
__global__ void __launch_bounds__(256, 4)
conv_mma_kernel(const float* __restrict__ Af,
                const __nv_bfloat16* __restrict__ Ahi,
                const __nv_bfloat16* __restrict__ Alo,
                const __nv_bfloat16* __restrict__ Whi,
                const __nv_bfloat16* __restrict__ Wlo,
                float* __restrict__ Yout,
                const float* __restrict__ gA, const float* __restrict__ bA,
                int COUT, int soff, int soffA, int chanoff)
{
    constexpr int NT = 64;
    constexpr int NCHUNK = CIN / 64;
    constexpr int NBUF   = (!CONVA && NCHUNK >= 4) ? 2 : 1;
    constexpr int NFRAG  = NT / 16;          // 4
    constexpr int CHUNKB = (2 * 128 + 2 * NT) * 128;   // 49152
    constexpr int OFF_BHI_ = 2 * 128 * 128;
    constexpr int OFF_BLO_ = OFF_BHI_ + NT * 128;
    constexpr int OFF_STAT = NBUF * CHUNKB;
    constexpr int OFF_SC   = OFF_STAT + 8 * NT;
    constexpr int BITERS   = NT * 8 / 256;   // 2
    constexpr int LDT      = NT + 4;

    extern __shared__ __align__(16) char sm[];
    const uint32_t sb = smem_to_u32(sm);

    const int tid  = threadIdx.x;
    const int wid  = tid >> 5, lane = tid & 31;
    const int wm   = wid & 3, wn = wid >> 2;
    const int n0   = blockIdx.x * NT;
    const int m0   = blockIdx.y * 128;

    float* ssumf = (float*)(sm + OFF_STAT);
    float* ssqf  = ssumf + NT;
    for (int j = tid; j < 2 * NT; j += 256) ssumf[j] = 0.0f;

    float* ascale = (float*)(sm + OFF_SC);
    float* abias  = ascale + (CONVA ? CIN : 0);
    if (CONVA) {
        if (tid < CIN) {
            double mu  = (double)g_sum[soffA + tid] / (double)M1_;
            double var = (double)g_sq [soffA + tid] / (double)M1_ - mu * mu;
            var = var > 0.0 ? var : 0.0;
            float sc = gA[tid] * (float)(1.0 / sqrt(var + 1e-5));
            ascale[tid] = sc;
            abias [tid] = bA[tid] - (float)mu * sc;
        }
        __syncthreads();
    }

    const int g = lane >> 3, l = lane & 7;
    const int rA = ((g & 1) ? 8 : 0) + l;
    const int kA = (g & 2) ? 8 : 0;
    const int rB = ((g & 2) ? 8 : 0) + l;
    const int kB = (g & 1) ? 8 : 0;

    float acc[2][NFRAG][4];
    #pragma unroll
    for (int mf = 0; mf < 2; mf++)
        #pragma unroll
        for (int nf = 0; nf < NFRAG; nf++)
            #pragma unroll
            for (int i = 0; i < 4; i++) acc[mf][nf][i] = 0.0f;

    auto issue_b = [&](int chunk, uint32_t sbb) {
        const int kt = chunk * 64;
        #pragma unroll
        for (int it = 0; it < BITERS; it++) {
            int e = tid + it * 256;
            int n = e >> 3, u = e & 7;
            size_t gofs = (size_t)(n0 + n) * CIN + kt + u * 8;
            uint32_t so = swz(n, u);
            cpa16(sbb + OFF_BHI_ + so, Whi + gofs);
            cpa16(sbb + OFF_BLO_ + so, Wlo + gofs);
        }
    };
    auto issue_a_async = [&](int chunk, uint32_t sbb) {
        const int kt = chunk * 64;
        #pragma unroll
        for (int it = 0; it < 4; it++) {
            int e = tid + it * 256;
            int m = e >> 3, u = e & 7;
            size_t gofs = (size_t)(m0 + m) * CIN + kt + u * 8;
            uint32_t so = swz(m, u);
            cpa16(sbb + so,              Ahi + gofs);
            cpa16(sbb + 128 * 128 + so,  Alo + gofs);
        }
    };
    auto load_a_conv = [&](int chunk) {
        const int kt = chunk * 64;
        float4 r[8];
        #pragma unroll
        for (int it = 0; it < 4; it++) {
            int e = tid + it * 256;
            int m = e >> 3, u = e & 7;
            const float* yp = Af + (size_t)(m0 + m) * CIN + kt + u * 8;
            r[2 * it]     = *(const float4*)(yp);
            r[2 * it + 1] = *(const float4*)(yp + 4);
        }
        #pragma unroll
        for (int it = 0; it < 4; it++) {
            int e = tid + it * 256;
            int m = e >> 3, u = e & 7;
            float f[8];
            *(float4*)(f)     = r[2 * it];
            *(float4*)(f + 4) = r[2 * it + 1];
            uint32_t hw[4], lw[4];
            #pragma unroll
            for (int i = 0; i < 4; i++) {
                int c = kt + u * 8 + 2 * i;
                float v0 = f[2 * i]     * ascale[c]     + abias[c];
                float v1 = f[2 * i + 1] * ascale[c + 1] + abias[c + 1];
                v0 = (v0 >= 0.0f) ? v0 : 0.2f * v0;
                v1 = (v1 >= 0.0f) ? v1 : 0.2f * v1;
                hw[i] = pack_bf2(v0, v1, lw[i]);
            }
            uint32_t so = swz(m, u);
            *(uint4*)(sm + so)             = make_uint4(hw[0], hw[1], hw[2], hw[3]);
            *(uint4*)(sm + 128 * 128 + so) = make_uint4(lw[0], lw[1], lw[2], lw[3]);
        }
    };
    auto do_mma = [&](uint32_t sbb) {
        #pragma unroll
        for (int ks = 0; ks < 4; ks++) {
            uint32_t ahi[2][4], alo[2][4];
            #pragma unroll
            for (int mf = 0; mf < 2; mf++) {
                int row = wm * 32 + mf * 16 + rA;
                uint32_t ao = swz(row, ks * 2 + (kA >> 3));
                ldsm_x4(sbb + ao, ahi[mf]);
                ldsm_x4(sbb + 128 * 128 + ao, alo[mf]);
            }
            uint32_t bhi[NFRAG][2], blo[NFRAG][2];
            #pragma unroll
            for (int nf2 = 0; nf2 < NFRAG / 2; nf2++) {
                int row = wn * (NT / 2) + nf2 * 16 + rB;
                uint32_t bo = swz(row, ks * 2 + (kB >> 3));
                uint32_t t[4];
                ldsm_x4(sbb + OFF_BHI_ + bo, t);
                bhi[2 * nf2][0] = t[0]; bhi[2 * nf2][1] = t[1];
                bhi[2 * nf2 + 1][0] = t[2]; bhi[2 * nf2 + 1][1] = t[3];
                ldsm_x4(sbb + OFF_BLO_ + bo, t);
                blo[2 * nf2][0] = t[0]; blo[2 * nf2][1] = t[1];
                blo[2 * nf2 + 1][0] = t[2]; blo[2 * nf2 + 1][1] = t[3];
            }
            #pragma unroll
            for (int mf = 0; mf < 2; mf++)
                #pragma unroll
                for (int nf = 0; nf < NFRAG; nf++) {
                    mma_bf16(acc[mf][nf], ahi[mf], bhi[nf]);
                    mma_bf16(acc[mf][nf], ahi[mf], blo[nf]);
                    mma_bf16(acc[mf][nf], alo[mf], bhi[nf]);
                }
        }
    };

    if (CONVA) {
        for (int chunk = 0; chunk < NCHUNK; chunk++) {
            issue_b(chunk, sb);
            asm volatile("cp.async.commit_group;" ::: "memory");
            load_a_conv(chunk);
            asm volatile("cp.async.wait_group 0;" ::: "memory");
            __syncthreads();
            do_mma(sb);
            __syncthreads();
        }
    } else {
        issue_a_async(0, sb);
        issue_b(0, sb);
        asm volatile("cp.async.commit_group;" ::: "memory");
        for (int chunk = 0; chunk < NCHUNK; chunk++) {
            const int buf = (NBUF == 2) ? (chunk & 1) : 0;
            if (NBUF == 2 && chunk + 1 < NCHUNK) {
                uint32_t nb = sb + ((chunk + 1) & 1) * CHUNKB;
                issue_a_async(chunk + 1, nb);
                issue_b(chunk + 1, nb);
                asm volatile("cp.async.commit_group;" ::: "memory");
                asm volatile("cp.async.wait_group 1;" ::: "memory");
            } else {
                asm volatile("cp.async.wait_group 0;" ::: "memory");
            }
            __syncthreads();
            do_mma(sb + buf * CHUNKB);
            __syncthreads();
            if (NBUF == 1 && chunk + 1 < NCHUNK) {
                issue_a_async(chunk + 1, sb);
                issue_b(chunk + 1, sb);
                asm volatile("cp.async.commit_group;" ::: "memory");
            }
        }
    }

    // ---- epilogue ----
    float* yt = (float*)sm;
    const int qr = lane >> 2, qc = (lane & 3) * 2;
    #pragma unroll
    for (int nf = 0; nf < NFRAG; nf++) {
        const int coln = wn * (NT / 2) + nf * 8 + qc;
        float s0 = 0.0f, s1 = 0.0f, q0 = 0.0f, q1 = 0.0f;
        #pragma unroll
        for (int mf = 0; mf < 2; mf++) {
            float c0 = acc[mf][nf][0], c1 = acc[mf][nf][1];
            float c2 = acc[mf][nf][2], c3 = acc[mf][nf][3];
            int row = wm * 32 + mf * 16 + qr;
            if (WRITE_Y) {
                *(float2*)&Yout[(size_t)(m0 + row) * COUT + n0 + coln]     = make_float2(c0, c1);
                *(float2*)&Yout[(size_t)(m0 + row + 8) * COUT + n0 + coln] = make_float2(c2, c3);
            }
            if (DO_MAX) {
                *(float2*)&yt[row * LDT + coln]       = make_float2(c0, c1);
                *(float2*)&yt[(row + 8) * LDT + coln] = make_float2(c2, c3);
            }
            s0 += c0 + c2;  s1 += c1 + c3;
            q0 += c0 * c0 + c2 * c2;
            q1 += c1 * c1 + c3 * c3;
        }
        #pragma unroll
        for (int off = 16; off >= 4; off >>= 1) {
            s0 += __shfl_down_sync(0xffffffffu, s0, off);
            s1 += __shfl_down_sync(0xffffffffu, s1, off);
            q0 += __shfl_down_sync(0xffffffffu, q0, off);
            q1 += __shfl_down_sync(0xffffffffu, q1, off);
        }
        if (lane < 4) {
            atomicAdd(&ssumf[coln],     s0);
            atomicAdd(&ssumf[coln + 1], s1);
            atomicAdd(&ssqf [coln],     q0);
            atomicAdd(&ssqf [coln + 1], q1);
        }
    }

    if (DO_MAX) {
        __syncthreads();
        const int pbase = m0 / KNN_;
        for (int item = tid; item < 8 * NT; item += 256) {
            int s  = item / NT;
            int ch = item - s * NT;
            int p  = pbase + s;
            int rs = p * KNN_ - m0;
            int re = rs + KNN_;
            rs = rs < 0 ? 0 : rs;
            re = re > 128 ? 128 : re;
            if (rs < re) {
                float mx = yt[rs * LDT + ch];
                for (int r = rs + 1; r < re; r++) mx = fmaxf(mx, yt[r * LDT + ch]);
                atomicMax(&g_ymax[(size_t)p * 512 + chanoff + n0 + ch], enc_f(mx));
            }
        }
    }

    __syncthreads();
    for (int j = tid; j < NT; j += 256) {
        atomicAdd(&g_sum[soff + n0 + j], ssumf[j]);
        atomicAdd(&g_sq [soff + n0 + j], ssqf[j]);
    }
}

template<int CIN, bool CONVA>
constexpr int conv_smem_size() {
    return ((!CONVA && CIN / 64 >= 4) ? 2 : 1) * (2 * 128 + 2 * 64) * 128
           + 8 * 64 + (CONVA ? 8 * CIN : 0);
}

// ---------------------------------------------------------------------------
__global__ void finalize14_kernel(
    const float* __restrict__ g1, const float* __restrict__ b1,
    const float* __restrict__ g2, const float* __restrict__ b2,
    const float* __restrict__ g3, const float* __restrict__ b3,
    const float* __restrict__ g4, const float* __restrict__ b4)
{
    int o = blockIdx.x * 256 + threadIdx.x;
    if (o >= 512) return;
    const float* g; const float* bb; int loc;
    if      (o < 64)  { g = g1; bb = b1; loc = o; }
    else if (o < 128) { g = g2; bb = b2; loc = o - 64; }
    else if (o < 256) { g = g3; bb = b3; loc = o - 128; }
    else              { g = g4; bb = b4; loc = o - 256; }
    double mu  = (double)g_sum[o] / (double)M1_;
    double var = (double)g_sq [o] / (double)M1_ - mu * mu;
    var = var > 0.0 ? var : 0.0;
    float sc = g[loc] * (float)(1.0 / sqrt(var + 1e-5));
    g_scale[o] = sc;
    g_bias [o] = bb[loc] - (float)mu * sc;
}

__global__ void finalize5_kernel(const float* __restrict__ g5,
                                 const float* __restrict__ b5)
{
    int o = blockIdx.x * 256 + threadIdx.x;
    if (o >= 1024) return;
    double mu  = (double)g_sum[512 + o] / (double)ROWS_;
    double var = (double)g_sq [512 + o] / (double)ROWS_ - mu * mu;
    var = var > 0.0 ? var : 0.0;
    float sc = g5[o] * (float)(1.0 / sqrt(var + 1e-5));
    g_scale[512 + o] = sc;
    g_bias [512 + o] = b5[o] - (float)mu * sc;
}

// ---------------------------------------------------------------------------
__global__ void __launch_bounds__(256)
apply_max_all_kernel()
{
    int t = blockIdx.x * blockDim.x + threadIdx.x;
    int o = (t & 255) * 2;
    int r = t >> 8;
    float sc0 = g_scale[o],     bi0 = g_bias[o];
    float sc1 = g_scale[o + 1], bi1 = g_bias[o + 1];
    uint2 e = *(const uint2*)&g_ymax[(size_t)r * 512 + o];
    float v0 = dec_f(e.x) * sc0 + bi0; v0 = (v0 >= 0.0f) ? v0 : 0.2f * v0;
    float v1 = dec_f(e.y) * sc1 + bi1; v1 = (v1 >= 0.0f) ? v1 : 0.2f * v1;
    size_t cidx = (size_t)r * 512 + o;
    uint32_t lo;
    uint32_t hi = pack_bf2(v0, v1, lo);
    *(uint32_t*)&g_cathi[cidx] = hi;
    *(uint32_t*)&g_catlo[cidx] = lo;
}

// ---------------------------------------------------------------------------
__global__ void __launch_bounds__(256)
apply5_kernel(float* __restrict__ out)
{
    __shared__ float tile[32][33];
    const int b  = blockIdx.z;
    const int o0 = blockIdx.x * 32;
    const int n0 = blockIdx.y * 32;
    const int txx = threadIdx.x, tyy = threadIdx.y;

    float sc = g_scale[512 + o0 + txx], bi = g_bias[512 + o0 + txx];
    #pragma unroll
    for (int i = 0; i < 4; i++) {
        int n = n0 + tyy + i * 8;
        float v = g_y5[((size_t)(b * N_ + n)) * 1024 + o0 + txx];
        v = v * sc + bi;
        v = (v >= 0.0f) ? v : 0.2f * v;
        tile[tyy + i * 8][txx] = v;
    }
    __syncthreads();
    #pragma unroll
    for (int i = 0; i < 4; i++) {
        int o = o0 + tyy + i * 8;
        out[((size_t)(b * 1024 + o)) * N_ + n0 + txx] = tile[txx][tyy + i * 8];
    }
}

// ---------------------------------------------------------------------------
extern "C" void kernel_launch(void* const* d_in, const int* in_sizes, int n_in,
                              void* d_out, int out_size)
{
    const float* x  = (const float*)d_in[0];
    const float* W1 = (const float*)d_in[1];
    const float* g1 = (const float*)d_in[2];
    const float* b1 = (const float*)d_in[3];
    const float* W2 = (const float*)d_in[4];
    const float* g2 = (const float*)d_in[5];
    const float* b2 = (const float*)d_in[6];
    const float* W3 = (const float*)d_in[7];
    const float* g3 = (const float*)d_in[8];
    const float* b3 = (const float*)d_in[9];
    const float* W4 = (const float*)d_in[10];
    const float* g4 = (const float*)d_in[11];
    const float* b4 = (const float*)d_in[12];
    const float* W5 = (const float*)d_in[13];
    const float* g5 = (const float*)d_in[14];
    const float* b5 = (const float*)d_in[15];
    float* out = (float*)d_out;

    void *p_ya, *p_yb, *p_y5, *p_chi, *p_clo, *p_whi, *p_wlo;
    cudaGetSymbolAddress(&p_ya,  g_ya);
    cudaGetSymbolAddress(&p_yb,  g_yb);
    cudaGetSymbolAddress(&p_y5,  g_y5);
    cudaGetSymbolAddress(&p_chi, g_cathi);
    cudaGetSymbolAddress(&p_clo, g_catlo);
    cudaGetSymbolAddress(&p_whi, g_whi);
    cudaGetSymbolAddress(&p_wlo, g_wlo);
    float* f_ya = (float*)p_ya;
    float* f_yb = (float*)p_yb;
    float* f_y5 = (float*)p_y5;
    const __nv_bfloat16* f_chi = (const __nv_bfloat16*)p_chi;
    const __nv_bfloat16* f_clo = (const __nv_bfloat16*)p_clo;
    const __nv_bfloat16* f_whi = (const __nv_bfloat16*)p_whi;
    const __nv_bfloat16* f_wlo = (const __nv_bfloat16*)p_wlo;

    cudaFuncSetAttribute(knn_conv1_kernel, cudaFuncAttributeMaxDynamicSharedMemorySize, 92160);
    cudaFuncSetAttribute((conv_mma_kernel<64, true, true, true>),
                         cudaFuncAttributeMaxDynamicSharedMemorySize, conv_smem_size<64, true>());
    cudaFuncSetAttribute((conv_mma_kernel<128, true, false, true>),
                         cudaFuncAttributeMaxDynamicSharedMemorySize, conv_smem_size<128, true>());
    cudaFuncSetAttribute((conv_mma_kernel<512, false, true, false>),
                         cudaFuncAttributeMaxDynamicSharedMemorySize, conv_smem_size<512, false>());

    const int MB = M1_ / 128;   // 2560

    // 0: zero BN stats
    init_stats_kernel<<<6, 256>>>();

    // 1: knn + conv1 + stats1 + ymax1 + W split + ymax init
    knn_conv1_kernel<<<dim3(N_ / 8, B_), 256, 92160>>>(x, W1, W2, W3, W4, W5);

    // 2: stage 2 (64 -> 64)
    conv_mma_kernel<64, true, true, true>
        <<<dim3(1, MB), 256, conv_smem_size<64, true>()>>>(
        f_ya, nullptr, nullptr, f_whi + W2_OFF, f_wlo + W2_OFF, f_yb,
        g1, b1, 64, 64, 0, 64);

    // 3: stage 3 (64 -> 128)   <-- ncu capture slot
    conv_mma_kernel<64, true, true, true>
        <<<dim3(2, MB), 256, conv_smem_size<64, true>()>>>(
        f_yb, nullptr, nullptr, f_whi + W3_OFF, f_wlo + W3_OFF, f_ya,
        g2, b2, 128, 128, 64, 128);

    // 4: stage 4 (128 -> 256, max only)
    conv_mma_kernel<128, true, false, true>
        <<<dim3(4, MB), 256, conv_smem_size<128, true>()>>>(
        f_ya, nullptr, nullptr, f_whi + W4_OFF, f_wlo + W4_OFF, nullptr,
        g3, b3, 256, 256, 128, 256);

    // 5-6: finalize stages 1-4 + single cat pass
    finalize14_kernel<<<2, 256>>>(g1, b1, g2, b2, g3, b3, g4, b4);
    apply_max_all_kernel<<<(ROWS_ * 256) / 256, 256>>>();

    // 7: stage 5 (512 -> 1024)
    conv_mma_kernel<512, false, true, false>
        <<<dim3(16, ROWS_ / 128), 256, conv_smem_size<512, false>()>>>(
        nullptr, f_chi, f_clo, f_whi + W5_OFF, f_wlo + W5_OFF, f_y5,
        nullptr, nullptr, 1024, 512, 0, 0);
    finalize5_kernel<<<4, 256>>>(g5, b5);
    apply5_kernel<<<dim3(32, 64, B_), dim3(32, 8)>>>(out);

    (void)in_sizes; (void)n_in; (void)out_size;
}

// round 15
// speedup vs baseline: 1.0134x; 1.0134x over previous
#include <cuda_runtime.h>
#include <cuda_bf16.h>
#include <math.h>
#include <stdint.h>

// ---------------------------------------------------------------------------
// DGCNN forward, B=8, C=3, N=2048, K=20
// knn+conv1 fused; mma.sync bf16-split convs (NT=64, SW128-swizzled smem,
// per-stage blocks/SM bound); loader-fused BN+LReLU+split; fused k-max.
// ---------------------------------------------------------------------------

#define B_      8
#define N_      2048
#define KNN_    20
#define ROWS_   (B_ * N_)                 // 16384
#define M1_     (ROWS_ * KNN_)            // 327680

#define W2_OFF  0
#define W3_OFF  4096
#define W4_OFF  12288
#define W5_OFF  45056
#define W_TOTAL 569344

// Static device scratch
__device__ float          g_ya[M1_ * 128];
__device__ float          g_yb[M1_ * 64];
__device__ float          g_y5[ROWS_ * 1024];
__device__ unsigned int   g_ymax[ROWS_ * 512];
__device__ __nv_bfloat16  g_cathi[ROWS_ * 512];
__device__ __nv_bfloat16  g_catlo[ROWS_ * 512];
__device__ __nv_bfloat16  g_whi[W_TOTAL];
__device__ __nv_bfloat16  g_wlo[W_TOTAL];
__device__ float  g_sum[1536];
__device__ float  g_sq [1536];
__device__ float  g_scale[1536];
__device__ float  g_bias [1536];

// ---------------------------------------------------------------------------
__device__ __forceinline__ uint32_t smem_to_u32(const void* p) {
    uint32_t a;
    asm("{ .reg .u64 t; cvta.to.shared.u64 t, %1; cvt.u32.u64 %0, t; }" : "=r"(a) : "l"(p));
    return a;
}
__device__ __forceinline__ void ldsm_x4(uint32_t addr, uint32_t r[4]) {
    asm volatile("ldmatrix.sync.aligned.m8n8.x4.shared.b16 {%0,%1,%2,%3}, [%4];"
                 : "=r"(r[0]), "=r"(r[1]), "=r"(r[2]), "=r"(r[3]) : "r"(addr));
}
__device__ __forceinline__ void mma_bf16(float c[4], const uint32_t a[4], const uint32_t b[2]) {
    asm volatile("mma.sync.aligned.m16n8k16.row.col.f32.bf16.bf16.f32 "
                 "{%0,%1,%2,%3}, {%4,%5,%6,%7}, {%8,%9}, {%0,%1,%2,%3};"
                 : "+f"(c[0]), "+f"(c[1]), "+f"(c[2]), "+f"(c[3])
                 : "r"(a[0]), "r"(a[1]), "r"(a[2]), "r"(a[3]), "r"(b[0]), "r"(b[1]));
}
__device__ __forceinline__ void cpa16(uint32_t saddr, const void* g) {
    asm volatile("cp.async.cg.shared.global [%0], [%1], 16;" :: "r"(saddr), "l"(g));
}
__device__ __forceinline__ unsigned int enc_f(float f) {
    unsigned int b = __float_as_uint(f);
    return b ^ ((unsigned int)((int)b >> 31) | 0x80000000u);
}
__device__ __forceinline__ float dec_f(unsigned int e) {
    unsigned int b = (e & 0x80000000u) ? (e ^ 0x80000000u) : ~e;
    return __uint_as_float(b);
}
__device__ __forceinline__ uint32_t pack_bf2(float v0, float v1, uint32_t& lo) {
    __nv_bfloat16 h0 = __float2bfloat16_rn(v0);
    __nv_bfloat16 h1 = __float2bfloat16_rn(v1);
    __nv_bfloat16 l0 = __float2bfloat16_rn(v0 - __bfloat162float(h0));
    __nv_bfloat16 l1 = __float2bfloat16_rn(v1 - __bfloat162float(h1));
    lo = (uint32_t)__bfloat16_as_ushort(l0) | ((uint32_t)__bfloat16_as_ushort(l1) << 16);
    return (uint32_t)__bfloat16_as_ushort(h0) | ((uint32_t)__bfloat16_as_ushort(h1) << 16);
}
__device__ __forceinline__ uint32_t swz(int m, int u) {
    return (uint32_t)(m * 128 + ((u ^ (m & 7)) << 4));
}

// ---------------------------------------------------------------------------
__global__ void init_stats_kernel() {
    int t = blockIdx.x * 256 + threadIdx.x;
    if (t < 1536) { g_sum[t] = 0.0f; g_sq[t] = 0.0f; }
}

// ---------------------------------------------------------------------------
// kNN + edge features + FUSED conv1 (6->64) + stats1 + ymax1 (+ W split etc).
// ---------------------------------------------------------------------------
__global__ void __launch_bounds__(256) knn_conv1_kernel(
    const float* __restrict__ x,  const float* __restrict__ W1,
    const float* __restrict__ W2, const float* __restrict__ W3,
    const float* __restrict__ W4, const float* __restrict__ W5)
{
    extern __shared__ float ksm[];
    float* xs0  = ksm;
    float* xs1  = ksm + 2048;
    float* xs2  = ksm + 4096;
    float* dist = ksm + 6144;
    __shared__ int   selw[8][KNN_];
    __shared__ float W1s[384];
    __shared__ float bsum[64], bsq[64];

    const int b   = blockIdx.y;
    const int tid = threadIdx.x;
    const int w   = tid >> 5, lane = tid & 31;
    const int il  = blockIdx.x * 8 + w;
    const float* xb = x + (size_t)b * 3 * N_;

    const int fb  = blockIdx.y * gridDim.x + blockIdx.x;
    const int gt  = fb * 256 + tid;
    const int NTH = gridDim.x * gridDim.y * 256;
    for (int t = gt; t < W_TOTAL; t += NTH) {
        const float* src; int idx;
        if      (t < W3_OFF) { src = W2; idx = t; }
        else if (t < W4_OFF) { src = W3; idx = t - W3_OFF; }
        else if (t < W5_OFF) { src = W4; idx = t - W4_OFF; }
        else                 { src = W5; idx = t - W5_OFF; }
        float v = src[idx];
        __nv_bfloat16 h = __float2bfloat16_rn(v);
        g_whi[t] = h;
        g_wlo[t] = __float2bfloat16_rn(v - __bfloat162float(h));
    }
    const unsigned int NEG = enc_f(-3.4e38f);
    for (int idx = gt; idx < ROWS_ * 448; idx += NTH) {
        int r = idx / 448, c = idx - r * 448;
        g_ymax[(size_t)r * 512 + 64 + c] = NEG;
    }
    for (int t = tid; t < 384; t += 256) W1s[t] = W1[t];
    if (tid < 64) { bsum[tid] = 0.0f; bsq[tid] = 0.0f; }

    for (int j = tid; j < N_; j += 256) {
        xs0[j] = xb[j];
        xs1[j] = xb[N_ + j];
        xs2[j] = xb[2 * N_ + j];
    }
    __syncthreads();

    const float p0 = xs0[il], p1 = xs1[il], p2 = xs2[il];
    const float xxi = p0 * p0 + p1 * p1 + p2 * p2;
    float* dw = dist + w * 2048;

    for (int j = lane; j < N_; j += 32) {
        float q0 = xs0[j], q1 = xs1[j], q2 = xs2[j];
        float inner = p0 * q0 + p1 * q1 + p2 * q2;
        float xxj = q0 * q0 + q1 * q1 + q2 * q2;
        dw[j] = 2.0f * inner - xxi - xxj;
    }
    __syncwarp();

    for (int t = 0; t < KNN_; t++) {
        float v = -3.0e38f; int bj = N_;
        #pragma unroll 8
        for (int j = lane; j < N_; j += 32) {
            float d = dw[j];
            if (d > v || (d == v && j < bj)) { v = d; bj = j; }
        }
        #pragma unroll
        for (int s = 16; s > 0; s >>= 1) {
            float ov = __shfl_down_sync(0xffffffffu, v, s);
            int   oj = __shfl_down_sync(0xffffffffu, bj, s);
            if (ov > v || (ov == v && oj < bj)) { v = ov; bj = oj; }
        }
        bj = __shfl_sync(0xffffffffu, bj, 0);
        if (lane == 0) { selw[w][t] = bj; dw[bj] = -3.3e38f; }
        __syncwarp();
    }
    __syncwarp();

    const int p = b * N_ + il;
    float w0[6], w1[6];
    #pragma unroll
    for (int c = 0; c < 6; c++) {
        w0[c] = W1s[(2 * lane) * 6 + c];
        w1[c] = W1s[(2 * lane + 1) * 6 + c];
    }
    float s0 = 0.0f, s1 = 0.0f, q0 = 0.0f, q1 = 0.0f;
    float mx0 = -3.4e38f, mx1 = -3.4e38f;
    #pragma unroll 4
    for (int k = 0; k < KNN_; k++) {
        int j = selw[w][k];
        float e0 = xs0[j] - p0, e1 = xs1[j] - p1, e2 = xs2[j] - p2;
        float y0 = e0 * w0[0];
        y0 = fmaf(e1, w0[1], y0); y0 = fmaf(e2, w0[2], y0);
        y0 = fmaf(p0, w0[3], y0); y0 = fmaf(p1, w0[4], y0); y0 = fmaf(p2, w0[5], y0);
        float y1 = e0 * w1[0];
        y1 = fmaf(e1, w1[1], y1); y1 = fmaf(e2, w1[2], y1);
        y1 = fmaf(p0, w1[3], y1); y1 = fmaf(p1, w1[4], y1); y1 = fmaf(p2, w1[5], y1);
        *(float2*)&g_ya[((size_t)p * KNN_ + k) * 64 + 2 * lane] = make_float2(y0, y1);
        mx0 = fmaxf(mx0, y0); mx1 = fmaxf(mx1, y1);
        s0 += y0; s1 += y1;
        q0 = fmaf(y0, y0, q0); q1 = fmaf(y1, y1, q1);
    }
    g_ymax[(size_t)p * 512 + 2 * lane]     = enc_f(mx0);
    g_ymax[(size_t)p * 512 + 2 * lane + 1] = enc_f(mx1);
    atomicAdd(&bsum[2 * lane], s0);
    atomicAdd(&bsum[2 * lane + 1], s1);
    atomicAdd(&bsq [2 * lane], q0);
    atomicAdd(&bsq [2 * lane + 1], q1);
    __syncthreads();
    if (tid < 64) {
        atomicAdd(&g_sum[tid], bsum[tid]);
        atomicAdd(&g_sq [tid], bsq[tid]);
    }
}

// ---------------------------------------------------------------------------
// mma.sync bf16-split GEMM. NT=64, SW128 swizzled smem.
// MINB: per-stage blocks/SM bound (4 for CONVA stages, 2 for stage 5).
// ---------------------------------------------------------------------------
template<int CIN, bool CONVA, bool WRITE_Y, bool DO_MAX, int MINB>
__global__ void __launch_bounds__(256, MINB)
conv_mma_kernel(const float* __restrict__ Af,
                const __nv_bfloat16* __restrict__ Ahi,
                const __nv_bfloat16* __restrict__ Alo,
                const __nv_bfloat16* __restrict__ Whi,
                const __nv_bfloat16* __restrict__ Wlo,
                float* __restrict__ Yout,
                const float* __restrict__ gA, const float* __restrict__ bA,
                int COUT, int soff, int soffA, int chanoff)
{
    constexpr int NT = 64;
    constexpr int NCHUNK = CIN / 64;
    constexpr int NBUF   = (!CONVA && NCHUNK >= 4) ? 2 : 1;
    constexpr int NFRAG  = NT / 16;
    constexpr int CHUNKB = (2 * 128 + 2 * NT) * 128;
    constexpr int OFF_BHI_ = 2 * 128 * 128;
    constexpr int OFF_BLO_ = OFF_BHI_ + NT * 128;
    constexpr int OFF_STAT = NBUF * CHUNKB;
    constexpr int OFF_SC   = OFF_STAT + 8 * NT;
    constexpr int BITERS   = NT * 8 / 256;
    constexpr int LDT      = NT + 4;

    extern __shared__ __align__(16) char sm[];
    const uint32_t sb = smem_to_u32(sm);

    const int tid  = threadIdx.x;
    const int wid  = tid >> 5, lane = tid & 31;
    const int wm   = wid & 3, wn = wid >> 2;
    const int n0   = blockIdx.x * NT;
    const int m0   = blockIdx.y * 128;

    float* ssumf = (float*)(sm + OFF_STAT);
    float* ssqf  = ssumf + NT;
    for (int j = tid; j < 2 * NT; j += 256) ssumf[j] = 0.0f;

    float* ascale = (float*)(sm + OFF_SC);
    float* abias  = ascale + (CONVA ? CIN : 0);
    if (CONVA) {
        if (tid < CIN) {
            double mu  = (double)g_sum[soffA + tid] / (double)M1_;
            double var = (double)g_sq [soffA + tid] / (double)M1_ - mu * mu;
            var = var > 0.0 ? var : 0.0;
            float sc = gA[tid] * (float)(1.0 / sqrt(var + 1e-5));
            ascale[tid] = sc;
            abias [tid] = bA[tid] - (float)mu * sc;
        }
        __syncthreads();
    }

    const int g = lane >> 3, l = lane & 7;
    const int rA = ((g & 1) ? 8 : 0) + l;
    const int kA = (g & 2) ? 8 : 0;
    const int rB = ((g & 2) ? 8 : 0) + l;
    const int kB = (g & 1) ? 8 : 0;

    float acc[2][NFRAG][4];
    #pragma unroll
    for (int mf = 0; mf < 2; mf++)
        #pragma unroll
        for (int nf = 0; nf < NFRAG; nf++)
            #pragma unroll
            for (int i = 0; i < 4; i++) acc[mf][nf][i] = 0.0f;

    auto issue_b = [&](int chunk, uint32_t sbb) {
        const int kt = chunk * 64;
        #pragma unroll
        for (int it = 0; it < BITERS; it++) {
            int e = tid + it * 256;
            int n = e >> 3, u = e & 7;
            size_t gofs = (size_t)(n0 + n) * CIN + kt + u * 8;
            uint32_t so = swz(n, u);
            cpa16(sbb + OFF_BHI_ + so, Whi + gofs);
            cpa16(sbb + OFF_BLO_ + so, Wlo + gofs);
        }
    };
    auto issue_a_async = [&](int chunk, uint32_t sbb) {
        const int kt = chunk * 64;
        #pragma unroll
        for (int it = 0; it < 4; it++) {
            int e = tid + it * 256;
            int m = e >> 3, u = e & 7;
            size_t gofs = (size_t)(m0 + m) * CIN + kt + u * 8;
            uint32_t so = swz(m, u);
            cpa16(sbb + so,              Ahi + gofs);
            cpa16(sbb + 128 * 128 + so,  Alo + gofs);
        }
    };
    auto load_a_conv = [&](int chunk) {
        const int kt = chunk * 64;
        float4 r[8];
        #pragma unroll
        for (int it = 0; it < 4; it++) {
            int e = tid + it * 256;
            int m = e >> 3, u = e & 7;
            const float* yp = Af + (size_t)(m0 + m) * CIN + kt + u * 8;
            r[2 * it]     = *(const float4*)(yp);
            r[2 * it + 1] = *(const float4*)(yp + 4);
        }
        #pragma unroll
        for (int it = 0; it < 4; it++) {
            int e = tid + it * 256;
            int m = e >> 3, u = e & 7;
            float f[8];
            *(float4*)(f)     = r[2 * it];
            *(float4*)(f + 4) = r[2 * it + 1];
            uint32_t hw[4], lw[4];
            #pragma unroll
            for (int i = 0; i < 4; i++) {
                int c = kt + u * 8 + 2 * i;
                float v0 = f[2 * i]     * ascale[c]     + abias[c];
                float v1 = f[2 * i + 1] * ascale[c + 1] + abias[c + 1];
                v0 = (v0 >= 0.0f) ? v0 : 0.2f * v0;
                v1 = (v1 >= 0.0f) ? v1 : 0.2f * v1;
                hw[i] = pack_bf2(v0, v1, lw[i]);
            }
            uint32_t so = swz(m, u);
            *(uint4*)(sm + so)             = make_uint4(hw[0], hw[1], hw[2], hw[3]);
            *(uint4*)(sm + 128 * 128 + so) = make_uint4(lw[0], lw[1], lw[2], lw[3]);
        }
    };
    auto do_mma = [&](uint32_t sbb) {
        #pragma unroll
        for (int ks = 0; ks < 4; ks++) {
            uint32_t ahi[2][4], alo[2][4];
            #pragma unroll
            for (int mf = 0; mf < 2; mf++) {
                int row = wm * 32 + mf * 16 + rA;
                uint32_t ao = swz(row, ks * 2 + (kA >> 3));
                ldsm_x4(sbb + ao, ahi[mf]);
                ldsm_x4(sbb + 128 * 128 + ao, alo[mf]);
            }
            uint32_t bhi[NFRAG][2], blo[NFRAG][2];
            #pragma unroll
            for (int nf2 = 0; nf2 < NFRAG / 2; nf2++) {
                int row = wn * (NT / 2) + nf2 * 16 + rB;
                uint32_t bo = swz(row, ks * 2 + (kB >> 3));
                uint32_t t[4];
                ldsm_x4(sbb + OFF_BHI_ + bo, t);
                bhi[2 * nf2][0] = t[0]; bhi[2 * nf2][1] = t[1];
                bhi[2 * nf2 + 1][0] = t[2]; bhi[2 * nf2 + 1][1] = t[3];
                ldsm_x4(sbb + OFF_BLO_ + bo, t);
                blo[2 * nf2][0] = t[0]; blo[2 * nf2][1] = t[1];
                blo[2 * nf2 + 1][0] = t[2]; blo[2 * nf2 + 1][1] = t[3];
            }
            #pragma unroll
            for (int mf = 0; mf < 2; mf++)
                #pragma unroll
                for (int nf = 0; nf < NFRAG; nf++) {
                    mma_bf16(acc[mf][nf], ahi[mf], bhi[nf]);
                    mma_bf16(acc[mf][nf], ahi[mf], blo[nf]);
                    mma_bf16(acc[mf][nf], alo[mf], bhi[nf]);
                }
        }
    };

    if (CONVA) {
        for (int chunk = 0; chunk < NCHUNK; chunk++) {
            issue_b(chunk, sb);
            asm volatile("cp.async.commit_group;" ::: "memory");
            load_a_conv(chunk);
            asm volatile("cp.async.wait_group 0;" ::: "memory");
            __syncthreads();
            do_mma(sb);
            __syncthreads();
        }
    } else {
        issue_a_async(0, sb);
        issue_b(0, sb);
        asm volatile("cp.async.commit_group;" ::: "memory");
        for (int chunk = 0; chunk < NCHUNK; chunk++) {
            const int buf = (NBUF == 2) ? (chunk & 1) : 0;
            if (NBUF == 2 && chunk + 1 < NCHUNK) {
                uint32_t nb = sb + ((chunk + 1) & 1) * CHUNKB;
                issue_a_async(chunk + 1, nb);
                issue_b(chunk + 1, nb);
                asm volatile("cp.async.commit_group;" ::: "memory");
                asm volatile("cp.async.wait_group 1;" ::: "memory");
            } else {
                asm volatile("cp.async.wait_group 0;" ::: "memory");
            }
            __syncthreads();
            do_mma(sb + buf * CHUNKB);
            __syncthreads();
            if (NBUF == 1 && chunk + 1 < NCHUNK) {
                issue_a_async(chunk + 1, sb);
                issue_b(chunk + 1, sb);
                asm volatile("cp.async.commit_group;" ::: "memory");
            }
        }
    }

    // ---- epilogue ----
    float* yt = (float*)sm;
    const int qr = lane >> 2, qc = (lane & 3) * 2;
    #pragma unroll
    for (int nf = 0; nf < NFRAG; nf++) {
        const int coln = wn * (NT / 2) + nf * 8 + qc;
        float s0 = 0.0f, s1 = 0.0f, q0 = 0.0f, q1 = 0.0f;
        #pragma unroll
        for (int mf = 0; mf < 2; mf++) {
            float c0 = acc[mf][nf][0], c1 = acc[mf][nf][1];
            float c2 = acc[mf][nf][2], c3 = acc[mf][nf][3];
            int row = wm * 32 + mf * 16 + qr;
            if (WRITE_Y) {
                *(float2*)&Yout[(size_t)(m0 + row) * COUT + n0 + coln]     = make_float2(c0, c1);
                *(float2*)&Yout[(size_t)(m0 + row + 8) * COUT + n0 + coln] = make_float2(c2, c3);
            }
            if (DO_MAX) {
                *(float2*)&yt[row * LDT + coln]       = make_float2(c0, c1);
                *(float2*)&yt[(row + 8) * LDT + coln] = make_float2(c2, c3);
            }
            s0 += c0 + c2;  s1 += c1 + c3;
            q0 += c0 * c0 + c2 * c2;
            q1 += c1 * c1 + c3 * c3;
        }
        #pragma unroll
        for (int off = 16; off >= 4; off >>= 1) {
            s0 += __shfl_down_sync(0xffffffffu, s0, off);
            s1 += __shfl_down_sync(0xffffffffu, s1, off);
            q0 += __shfl_down_sync(0xffffffffu, q0, off);
            q1 += __shfl_down_sync(0xffffffffu, q1, off);
        }
        if (lane < 4) {
            atomicAdd(&ssumf[coln],     s0);
            atomicAdd(&ssumf[coln + 1], s1);
            atomicAdd(&ssqf [coln],     q0);
            atomicAdd(&ssqf [coln + 1], q1);
        }
    }

    if (DO_MAX) {
        __syncthreads();
        const int pbase = m0 / KNN_;
        for (int item = tid; item < 8 * NT; item += 256) {
            int s  = item / NT;
            int ch = item - s * NT;
            int p  = pbase + s;
            int rs = p * KNN_ - m0;
            int re = rs + KNN_;
            rs = rs < 0 ? 0 : rs;
            re = re > 128 ? 128 : re;
            if (rs < re) {
                float mx = yt[rs * LDT + ch];
                for (int r = rs + 1; r < re; r++) mx = fmaxf(mx, yt[r * LDT + ch]);
                atomicMax(&g_ymax[(size_t)p * 512 + chanoff + n0 + ch], enc_f(mx));
            }
        }
    }

    __syncthreads();
    for (int j = tid; j < NT; j += 256) {
        atomicAdd(&g_sum[soff + n0 + j], ssumf[j]);
        atomicAdd(&g_sq [soff + n0 + j], ssqf[j]);
    }
}

template<int CIN, bool CONVA>
constexpr int conv_smem_size() {
    return ((!CONVA && CIN / 64 >= 4) ? 2 : 1) * (2 * 128 + 2 * 64) * 128
           + 8 * 64 + (CONVA ? 8 * CIN : 0);
}

// ---------------------------------------------------------------------------
__global__ void finalize14_kernel(
    const float* __restrict__ g1, const float* __restrict__ b1,
    const float* __restrict__ g2, const float* __restrict__ b2,
    const float* __restrict__ g3, const float* __restrict__ b3,
    const float* __restrict__ g4, const float* __restrict__ b4)
{
    int o = blockIdx.x * 256 + threadIdx.x;
    if (o >= 512) return;
    const float* g; const float* bb; int loc;
    if      (o < 64)  { g = g1; bb = b1; loc = o; }
    else if (o < 128) { g = g2; bb = b2; loc = o - 64; }
    else if (o < 256) { g = g3; bb = b3; loc = o - 128; }
    else              { g = g4; bb = b4; loc = o - 256; }
    double mu  = (double)g_sum[o] / (double)M1_;
    double var = (double)g_sq [o] / (double)M1_ - mu * mu;
    var = var > 0.0 ? var : 0.0;
    float sc = g[loc] * (float)(1.0 / sqrt(var + 1e-5));
    g_scale[o] = sc;
    g_bias [o] = bb[loc] - (float)mu * sc;
}

__global__ void finalize5_kernel(const float* __restrict__ g5,
                                 const float* __restrict__ b5)
{
    int o = blockIdx.x * 256 + threadIdx.x;
    if (o >= 1024) return;
    double mu  = (double)g_sum[512 + o] / (double)ROWS_;
    double var = (double)g_sq [512 + o] / (double)ROWS_ - mu * mu;
    var = var > 0.0 ? var : 0.0;
    float sc = g5[o] * (float)(1.0 / sqrt(var + 1e-5));
    g_scale[512 + o] = sc;
    g_bias [512 + o] = b5[o] - (float)mu * sc;
}

// ---------------------------------------------------------------------------
__global__ void __launch_bounds__(256)
apply_max_all_kernel()
{
    int t = blockIdx.x * blockDim.x + threadIdx.x;
    int o = (t & 255) * 2;
    int r = t >> 8;
    float sc0 = g_scale[o],     bi0 = g_bias[o];
    float sc1 = g_scale[o + 1], bi1 = g_bias[o + 1];
    uint2 e = *(const uint2*)&g_ymax[(size_t)r * 512 + o];
    float v0 = dec_f(e.x) * sc0 + bi0; v0 = (v0 >= 0.0f) ? v0 : 0.2f * v0;
    float v1 = dec_f(e.y) * sc1 + bi1; v1 = (v1 >= 0.0f) ? v1 : 0.2f * v1;
    size_t cidx = (size_t)r * 512 + o;
    uint32_t lo;
    uint32_t hi = pack_bf2(v0, v1, lo);
    *(uint32_t*)&g_cathi[cidx] = hi;
    *(uint32_t*)&g_catlo[cidx] = lo;
}

// ---------------------------------------------------------------------------
__global__ void __launch_bounds__(256)
apply5_kernel(float* __restrict__ out)
{
    __shared__ float tile[32][33];
    const int b  = blockIdx.z;
    const int o0 = blockIdx.x * 32;
    const int n0 = blockIdx.y * 32;
    const int txx = threadIdx.x, tyy = threadIdx.y;

    float sc = g_scale[512 + o0 + txx], bi = g_bias[512 + o0 + txx];
    #pragma unroll
    for (int i = 0; i < 4; i++) {
        int n = n0 + tyy + i * 8;
        float v = g_y5[((size_t)(b * N_ + n)) * 1024 + o0 + txx];
        v = v * sc + bi;
        v = (v >= 0.0f) ? v : 0.2f * v;
        tile[tyy + i * 8][txx] = v;
    }
    __syncthreads();
    #pragma unroll
    for (int i = 0; i < 4; i++) {
        int o = o0 + tyy + i * 8;
        out[((size_t)(b * 1024 + o)) * N_ + n0 + txx] = tile[txx][tyy + i * 8];
    }
}

// ---------------------------------------------------------------------------
extern "C" void kernel_launch(void* const* d_in, const int* in_sizes, int n_in,
                              void* d_out, int out_size)
{
    const float* x  = (const float*)d_in[0];
    const float* W1 = (const float*)d_in[1];
    const float* g1 = (const float*)d_in[2];
    const float* b1 = (const float*)d_in[3];
    const float* W2 = (const float*)d_in[4];
    const float* g2 = (const float*)d_in[5];
    const float* b2 = (const float*)d_in[6];
    const float* W3 = (const float*)d_in[7];
    const float* g3 = (const float*)d_in[8];
    const float* b3 = (const float*)d_in[9];
    const float* W4 = (const float*)d_in[10];
    const float* g4 = (const float*)d_in[11];
    const float* b4 = (const float*)d_in[12];
    const float* W5 = (const float*)d_in[13];
    const float* g5 = (const float*)d_in[14];
    const float* b5 = (const float*)d_in[15];
    float* out = (float*)d_out;

    void *p_ya, *p_yb, *p_y5, *p_chi, *p_clo, *p_whi, *p_wlo;
    cudaGetSymbolAddress(&p_ya,  g_ya);
    cudaGetSymbolAddress(&p_yb,  g_yb);
    cudaGetSymbolAddress(&p_y5,  g_y5);
    cudaGetSymbolAddress(&p_chi, g_cathi);
    cudaGetSymbolAddress(&p_clo, g_catlo);
    cudaGetSymbolAddress(&p_whi, g_whi);
    cudaGetSymbolAddress(&p_wlo, g_wlo);
    float* f_ya = (float*)p_ya;
    float* f_yb = (float*)p_yb;
    float* f_y5 = (float*)p_y5;
    const __nv_bfloat16* f_chi = (const __nv_bfloat16*)p_chi;
    const __nv_bfloat16* f_clo = (const __nv_bfloat16*)p_clo;
    const __nv_bfloat16* f_whi = (const __nv_bfloat16*)p_whi;
    const __nv_bfloat16* f_wlo = (const __nv_bfloat16*)p_wlo;

    cudaFuncSetAttribute(knn_conv1_kernel, cudaFuncAttributeMaxDynamicSharedMemorySize, 92160);
    cudaFuncSetAttribute((conv_mma_kernel<64, true, true, true, 4>),
                         cudaFuncAttributeMaxDynamicSharedMemorySize, conv_smem_size<64, true>());
    cudaFuncSetAttribute((conv_mma_kernel<128, true, false, true, 4>),
                         cudaFuncAttributeMaxDynamicSharedMemorySize, conv_smem_size<128, true>());
    cudaFuncSetAttribute((conv_mma_kernel<512, false, true, false, 2>),
                         cudaFuncAttributeMaxDynamicSharedMemorySize, conv_smem_size<512, false>());

    const int MB = M1_ / 128;   // 2560

    // 0: zero BN stats
    init_stats_kernel<<<6, 256>>>();

    // 1: knn + conv1 + stats1 + ymax1 + W split + ymax init
    knn_conv1_kernel<<<dim3(N_ / 8, B_), 256, 92160>>>(x, W1, W2, W3, W4, W5);

    // 2: stage 2 (64 -> 64)
    conv_mma_kernel<64, true, true, true, 4>
        <<<dim3(1, MB), 256, conv_smem_size<64, true>()>>>(
        f_ya, nullptr, nullptr, f_whi + W2_OFF, f_wlo + W2_OFF, f_yb,
        g1, b1, 64, 64, 0, 64);

    // 3: stage 3 (64 -> 128)   <-- ncu capture slot
    conv_mma_kernel<64, true, true, true, 4>
        <<<dim3(2, MB), 256, conv_smem_size<64, true>()>>>(
        f_yb, nullptr, nullptr, f_whi + W3_OFF, f_wlo + W3_OFF, f_ya,
        g2, b2, 128, 128, 64, 128);

    // 4: stage 4 (128 -> 256, max only)
    conv_mma_kernel<128, true, false, true, 4>
        <<<dim3(4, MB), 256, conv_smem_size<128, true>()>>>(
        f_ya, nullptr, nullptr, f_whi + W4_OFF, f_wlo + W4_OFF, nullptr,
        g3, b3, 256, 256, 128, 256);

    // 5-6: finalize stages 1-4 + single cat pass
    finalize14_kernel<<<2, 256>>>(g1, b1, g2, b2, g3, b3, g4, b4);
    apply_max_all_kernel<<<(ROWS_ * 256) / 256, 256>>>();

    // 7: stage 5 (512 -> 1024) — MINB=2: smem-capped anyway, avoid reg spills
    conv_mma_kernel<512, false, true, false, 2>
        <<<dim3(16, ROWS_ / 128), 256, conv_smem_size<512, false>()>>>(
        nullptr, f_chi, f_clo, f_whi + W5_OFF, f_wlo + W5_OFF, f_y5,
        nullptr, nullptr, 1024, 512, 0, 0);
    finalize5_kernel<<<4, 256>>>(g5, b5);
    apply5_kernel<<<dim3(32, 64, B_), dim3(32, 8)>>>(out);

    (void)in_sizes; (void)n_in; (void)out_size;
}

// round 16
// speedup vs baseline: 1.1376x; 1.1226x over previous
#include <cuda_runtime.h>
#include <cuda_bf16.h>
#include <math.h>
#include <stdint.h>

// ---------------------------------------------------------------------------
// DGCNN forward, B=8, C=3, N=2048, K=20
// knn+conv1 fused; mma.sync bf16-split convs (NT=64, SW128-swizzled smem,
// per-stage measured blocks/SM bound); loader-fused BN+LReLU+split; fused max.
// ---------------------------------------------------------------------------

#define B_      8
#define N_      2048
#define KNN_    20
#define ROWS_   (B_ * N_)                 // 16384
#define M1_     (ROWS_ * KNN_)            // 327680

#define W2_OFF  0
#define W3_OFF  4096
#define W4_OFF  12288
#define W5_OFF  45056
#define W_TOTAL 569344

// Static device scratch
__device__ float          g_ya[M1_ * 128];
__device__ float          g_yb[M1_ * 64];
__device__ float          g_y5[ROWS_ * 1024];
__device__ unsigned int   g_ymax[ROWS_ * 512];
__device__ __nv_bfloat16  g_cathi[ROWS_ * 512];
__device__ __nv_bfloat16  g_catlo[ROWS_ * 512];
__device__ __nv_bfloat16  g_whi[W_TOTAL];
__device__ __nv_bfloat16  g_wlo[W_TOTAL];
__device__ float  g_sum[1536];
__device__ float  g_sq [1536];
__device__ float  g_scale[1536];
__device__ float  g_bias [1536];

// ---------------------------------------------------------------------------
__device__ __forceinline__ uint32_t smem_to_u32(const void* p) {
    uint32_t a;
    asm("{ .reg .u64 t; cvta.to.shared.u64 t, %1; cvt.u32.u64 %0, t; }" : "=r"(a) : "l"(p));
    return a;
}
__device__ __forceinline__ void ldsm_x4(uint32_t addr, uint32_t r[4]) {
    asm volatile("ldmatrix.sync.aligned.m8n8.x4.shared.b16 {%0,%1,%2,%3}, [%4];"
                 : "=r"(r[0]), "=r"(r[1]), "=r"(r[2]), "=r"(r[3]) : "r"(addr));
}
__device__ __forceinline__ void mma_bf16(float c[4], const uint32_t a[4], const uint32_t b[2]) {
    asm volatile("mma.sync.aligned.m16n8k16.row.col.f32.bf16.bf16.f32 "
                 "{%0,%1,%2,%3}, {%4,%5,%6,%7}, {%8,%9}, {%0,%1,%2,%3};"
                 : "+f"(c[0]), "+f"(c[1]), "+f"(c[2]), "+f"(c[3])
                 : "r"(a[0]), "r"(a[1]), "r"(a[2]), "r"(a[3]), "r"(b[0]), "r"(b[1]));
}
__device__ __forceinline__ void cpa16(uint32_t saddr, const void* g) {
    asm volatile("cp.async.cg.shared.global [%0], [%1], 16;" :: "r"(saddr), "l"(g));
}
__device__ __forceinline__ unsigned int enc_f(float f) {
    unsigned int b = __float_as_uint(f);
    return b ^ ((unsigned int)((int)b >> 31) | 0x80000000u);
}
__device__ __forceinline__ float dec_f(unsigned int e) {
    unsigned int b = (e & 0x80000000u) ? (e ^ 0x80000000u) : ~e;
    return __uint_as_float(b);
}
__device__ __forceinline__ uint32_t pack_bf2(float v0, float v1, uint32_t& lo) {
    __nv_bfloat16 h0 = __float2bfloat16_rn(v0);
    __nv_bfloat16 h1 = __float2bfloat16_rn(v1);
    __nv_bfloat16 l0 = __float2bfloat16_rn(v0 - __bfloat162float(h0));
    __nv_bfloat16 l1 = __float2bfloat16_rn(v1 - __bfloat162float(h1));
    lo = (uint32_t)__bfloat16_as_ushort(l0) | ((uint32_t)__bfloat16_as_ushort(l1) << 16);
    return (uint32_t)__bfloat16_as_ushort(h0) | ((uint32_t)__bfloat16_as_ushort(h1) << 16);
}
__device__ __forceinline__ uint32_t swz(int m, int u) {
    return (uint32_t)(m * 128 + ((u ^ (m & 7)) << 4));
}

// ---------------------------------------------------------------------------
__global__ void init_stats_kernel() {
    int t = blockIdx.x * 256 + threadIdx.x;
    if (t < 1536) { g_sum[t] = 0.0f; g_sq[t] = 0.0f; }
}

// ---------------------------------------------------------------------------
// kNN + edge features + FUSED conv1 (6->64) + stats1 + ymax1 (+ W split etc).
// ---------------------------------------------------------------------------
__global__ void __launch_bounds__(256) knn_conv1_kernel(
    const float* __restrict__ x,  const float* __restrict__ W1,
    const float* __restrict__ W2, const float* __restrict__ W3,
    const float* __restrict__ W4, const float* __restrict__ W5)
{
    extern __shared__ float ksm[];
    float* xs0  = ksm;
    float* xs1  = ksm + 2048;
    float* xs2  = ksm + 4096;
    float* dist = ksm + 6144;
    __shared__ int   selw[8][KNN_];
    __shared__ float W1s[384];
    __shared__ float bsum[64], bsq[64];

    const int b   = blockIdx.y;
    const int tid = threadIdx.x;
    const int w   = tid >> 5, lane = tid & 31;
    const int il  = blockIdx.x * 8 + w;
    const float* xb = x + (size_t)b * 3 * N_;

    const int fb  = blockIdx.y * gridDim.x + blockIdx.x;
    const int gt  = fb * 256 + tid;
    const int NTH = gridDim.x * gridDim.y * 256;
    for (int t = gt; t < W_TOTAL; t += NTH) {
        const float* src; int idx;
        if      (t < W3_OFF) { src = W2; idx = t; }
        else if (t < W4_OFF) { src = W3; idx = t - W3_OFF; }
        else if (t < W5_OFF) { src = W4; idx = t - W4_OFF; }
        else                 { src = W5; idx = t - W5_OFF; }
        float v = src[idx];
        __nv_bfloat16 h = __float2bfloat16_rn(v);
        g_whi[t] = h;
        g_wlo[t] = __float2bfloat16_rn(v - __bfloat162float(h));
    }
    const unsigned int NEG = enc_f(-3.4e38f);
    for (int idx = gt; idx < ROWS_ * 448; idx += NTH) {
        int r = idx / 448, c = idx - r * 448;
        g_ymax[(size_t)r * 512 + 64 + c] = NEG;
    }
    for (int t = tid; t < 384; t += 256) W1s[t] = W1[t];
    if (tid < 64) { bsum[tid] = 0.0f; bsq[tid] = 0.0f; }

    for (int j = tid; j < N_; j += 256) {
        xs0[j] = xb[j];
        xs1[j] = xb[N_ + j];
        xs2[j] = xb[2 * N_ + j];
    }
    __syncthreads();

    const float p0 = xs0[il], p1 = xs1[il], p2 = xs2[il];
    const float xxi = p0 * p0 + p1 * p1 + p2 * p2;
    float* dw = dist + w * 2048;

    for (int j = lane; j < N_; j += 32) {
        float q0 = xs0[j], q1 = xs1[j], q2 = xs2[j];
        float inner = p0 * q0 + p1 * q1 + p2 * q2;
        float xxj = q0 * q0 + q1 * q1 + q2 * q2;
        dw[j] = 2.0f * inner - xxi - xxj;
    }
    __syncwarp();

    for (int t = 0; t < KNN_; t++) {
        float v = -3.0e38f; int bj = N_;
        #pragma unroll 8
        for (int j = lane; j < N_; j += 32) {
            float d = dw[j];
            if (d > v || (d == v && j < bj)) { v = d; bj = j; }
        }
        #pragma unroll
        for (int s = 16; s > 0; s >>= 1) {
            float ov = __shfl_down_sync(0xffffffffu, v, s);
            int   oj = __shfl_down_sync(0xffffffffu, bj, s);
            if (ov > v || (ov == v && oj < bj)) { v = ov; bj = oj; }
        }
        bj = __shfl_sync(0xffffffffu, bj, 0);
        if (lane == 0) { selw[w][t] = bj; dw[bj] = -3.3e38f; }
        __syncwarp();
    }
    __syncwarp();

    const int p = b * N_ + il;
    float w0[6], w1[6];
    #pragma unroll
    for (int c = 0; c < 6; c++) {
        w0[c] = W1s[(2 * lane) * 6 + c];
        w1[c] = W1s[(2 * lane + 1) * 6 + c];
    }
    float s0 = 0.0f, s1 = 0.0f, q0 = 0.0f, q1 = 0.0f;
    float mx0 = -3.4e38f, mx1 = -3.4e38f;
    #pragma unroll 4
    for (int k = 0; k < KNN_; k++) {
        int j = selw[w][k];
        float e0 = xs0[j] - p0, e1 = xs1[j] - p1, e2 = xs2[j] - p2;
        float y0 = e0 * w0[0];
        y0 = fmaf(e1, w0[1], y0); y0 = fmaf(e2, w0[2], y0);
        y0 = fmaf(p0, w0[3], y0); y0 = fmaf(p1, w0[4], y0); y0 = fmaf(p2, w0[5], y0);
        float y1 = e0 * w1[0];
        y1 = fmaf(e1, w1[1], y1); y1 = fmaf(e2, w1[2], y1);
        y1 = fmaf(p0, w1[3], y1); y1 = fmaf(p1, w1[4], y1); y1 = fmaf(p2, w1[5], y1);
        *(float2*)&g_ya[((size_t)p * KNN_ + k) * 64 + 2 * lane] = make_float2(y0, y1);
        mx0 = fmaxf(mx0, y0); mx1 = fmaxf(mx1, y1);
        s0 += y0; s1 += y1;
        q0 = fmaf(y0, y0, q0); q1 = fmaf(y1, y1, q1);
    }
    g_ymax[(size_t)p * 512 + 2 * lane]     = enc_f(mx0);
    g_ymax[(size_t)p * 512 + 2 * lane + 1] = enc_f(mx1);
    atomicAdd(&bsum[2 * lane], s0);
    atomicAdd(&bsum[2 * lane + 1], s1);
    atomicAdd(&bsq [2 * lane], q0);
    atomicAdd(&bsq [2 * lane + 1], q1);
    __syncthreads();
    if (tid < 64) {
        atomicAdd(&g_sum[tid], bsum[tid]);
        atomicAdd(&g_sq [tid], bsq[tid]);
    }
}

// ---------------------------------------------------------------------------
// mma.sync bf16-split GEMM. NT=64, SW128 swizzled smem.
// MINB per stage: 4 for <64,CONVA> (measured faster), 3 elsewhere (R13 best).
// ---------------------------------------------------------------------------
template<int CIN, bool CONVA, bool WRITE_Y, bool DO_MAX, int MINB>
__global__ void __launch_bounds__(256, MINB)
conv_mma_kernel(const float* __restrict__ Af,
                const __nv_bfloat16* __restrict__ Ahi,
                const __nv_bfloat16* __restrict__ Alo,
                const __nv_bfloat16* __restrict__ Whi,
                const __nv_bfloat16* __restrict__ Wlo,
                float* __restrict__ Yout,
                const float* __restrict__ gA, const float* __restrict__ bA,
                int COUT, int soff, int soffA, int chanoff)
{
    constexpr int NT = 64;
    constexpr int NCHUNK = CIN / 64;
    constexpr int NBUF   = (!CONVA && NCHUNK >= 4) ? 2 : 1;
    constexpr int NFRAG  = NT / 16;
    constexpr int CHUNKB = (2 * 128 + 2 * NT) * 128;
    constexpr int OFF_BHI_ = 2 * 128 * 128;
    constexpr int OFF_BLO_ = OFF_BHI_ + NT * 128;
    constexpr int OFF_STAT = NBUF * CHUNKB;
    constexpr int OFF_SC   = OFF_STAT + 8 * NT;
    constexpr int BITERS   = NT * 8 / 256;
    constexpr int LDT      = NT + 4;

    extern __shared__ __align__(16) char sm[];
    const uint32_t sb = smem_to_u32(sm);

    const int tid  = threadIdx.x;
    const int wid  = tid >> 5, lane = tid & 31;
    const int wm   = wid & 3, wn = wid >> 2;
    const int n0   = blockIdx.x * NT;
    const int m0   = blockIdx.y * 128;

    float* ssumf = (float*)(sm + OFF_STAT);
    float* ssqf  = ssumf + NT;
    for (int j = tid; j < 2 * NT; j += 256) ssumf[j] = 0.0f;

    float* ascale = (float*)(sm + OFF_SC);
    float* abias  = ascale + (CONVA ? CIN : 0);
    if (CONVA) {
        if (tid < CIN) {
            double mu  = (double)g_sum[soffA + tid] / (double)M1_;
            double var = (double)g_sq [soffA + tid] / (double)M1_ - mu * mu;
            var = var > 0.0 ? var : 0.0;
            float sc = gA[tid] * (float)(1.0 / sqrt(var + 1e-5));
            ascale[tid] = sc;
            abias [tid] = bA[tid] - (float)mu * sc;
        }
        __syncthreads();
    }

    const int g = lane >> 3, l = lane & 7;
    const int rA = ((g & 1) ? 8 : 0) + l;
    const int kA = (g & 2) ? 8 : 0;
    const int rB = ((g & 2) ? 8 : 0) + l;
    const int kB = (g & 1) ? 8 : 0;

    float acc[2][NFRAG][4];
    #pragma unroll
    for (int mf = 0; mf < 2; mf++)
        #pragma unroll
        for (int nf = 0; nf < NFRAG; nf++)
            #pragma unroll
            for (int i = 0; i < 4; i++) acc[mf][nf][i] = 0.0f;

    auto issue_b = [&](int chunk, uint32_t sbb) {
        const int kt = chunk * 64;
        #pragma unroll
        for (int it = 0; it < BITERS; it++) {
            int e = tid + it * 256;
            int n = e >> 3, u = e & 7;
            size_t gofs = (size_t)(n0 + n) * CIN + kt + u * 8;
            uint32_t so = swz(n, u);
            cpa16(sbb + OFF_BHI_ + so, Whi + gofs);
            cpa16(sbb + OFF_BLO_ + so, Wlo + gofs);
        }
    };
    auto issue_a_async = [&](int chunk, uint32_t sbb) {
        const int kt = chunk * 64;
        #pragma unroll
        for (int it = 0; it < 4; it++) {
            int e = tid + it * 256;
            int m = e >> 3, u = e & 7;
            size_t gofs = (size_t)(m0 + m) * CIN + kt + u * 8;
            uint32_t so = swz(m, u);
            cpa16(sbb + so,              Ahi + gofs);
            cpa16(sbb + 128 * 128 + so,  Alo + gofs);
        }
    };
    auto load_a_conv = [&](int chunk) {
        const int kt = chunk * 64;
        float4 r[8];
        #pragma unroll
        for (int it = 0; it < 4; it++) {
            int e = tid + it * 256;
            int m = e >> 3, u = e & 7;
            const float* yp = Af + (size_t)(m0 + m) * CIN + kt + u * 8;
            r[2 * it]     = *(const float4*)(yp);
            r[2 * it + 1] = *(const float4*)(yp + 4);
        }
        #pragma unroll
        for (int it = 0; it < 4; it++) {
            int e = tid + it * 256;
            int m = e >> 3, u = e & 7;
            float f[8];
            *(float4*)(f)     = r[2 * it];
            *(float4*)(f + 4) = r[2 * it + 1];
            uint32_t hw[4], lw[4];
            #pragma unroll
            for (int i = 0; i < 4; i++) {
                int c = kt + u * 8 + 2 * i;
                float v0 = f[2 * i]     * ascale[c]     + abias[c];
                float v1 = f[2 * i + 1] * ascale[c + 1] + abias[c + 1];
                v0 = (v0 >= 0.0f) ? v0 : 0.2f * v0;
                v1 = (v1 >= 0.0f) ? v1 : 0.2f * v1;
                hw[i] = pack_bf2(v0, v1, lw[i]);
            }
            uint32_t so = swz(m, u);
            *(uint4*)(sm + so)             = make_uint4(hw[0], hw[1], hw[2], hw[3]);
            *(uint4*)(sm + 128 * 128 + so) = make_uint4(lw[0], lw[1], lw[2], lw[3]);
        }
    };
    auto do_mma = [&](uint32_t sbb) {
        #pragma unroll
        for (int ks = 0; ks < 4; ks++) {
            uint32_t ahi[2][4], alo[2][4];
            #pragma unroll
            for (int mf = 0; mf < 2; mf++) {
                int row = wm * 32 + mf * 16 + rA;
                uint32_t ao = swz(row, ks * 2 + (kA >> 3));
                ldsm_x4(sbb + ao, ahi[mf]);
                ldsm_x4(sbb + 128 * 128 + ao, alo[mf]);
            }
            uint32_t bhi[NFRAG][2], blo[NFRAG][2];
            #pragma unroll
            for (int nf2 = 0; nf2 < NFRAG / 2; nf2++) {
                int row = wn * (NT / 2) + nf2 * 16 + rB;
                uint32_t bo = swz(row, ks * 2 + (kB >> 3));
                uint32_t t[4];
                ldsm_x4(sbb + OFF_BHI_ + bo, t);
                bhi[2 * nf2][0] = t[0]; bhi[2 * nf2][1] = t[1];
                bhi[2 * nf2 + 1][0] = t[2]; bhi[2 * nf2 + 1][1] = t[3];
                ldsm_x4(sbb + OFF_BLO_ + bo, t);
                blo[2 * nf2][0] = t[0]; blo[2 * nf2][1] = t[1];
                blo[2 * nf2 + 1][0] = t[2]; blo[2 * nf2 + 1][1] = t[3];
            }
            #pragma unroll
            for (int mf = 0; mf < 2; mf++)
                #pragma unroll
                for (int nf = 0; nf < NFRAG; nf++) {
                    mma_bf16(acc[mf][nf], ahi[mf], bhi[nf]);
                    mma_bf16(acc[mf][nf], ahi[mf], blo[nf]);
                    mma_bf16(acc[mf][nf], alo[mf], bhi[nf]);
                }
        }
    };

    if (CONVA) {
        for (int chunk = 0; chunk < NCHUNK; chunk++) {
            issue_b(chunk, sb);
            asm volatile("cp.async.commit_group;" ::: "memory");
            load_a_conv(chunk);
            asm volatile("cp.async.wait_group 0;" ::: "memory");
            __syncthreads();
            do_mma(sb);
            __syncthreads();
        }
    } else {
        issue_a_async(0, sb);
        issue_b(0, sb);
        asm volatile("cp.async.commit_group;" ::: "memory");
        for (int chunk = 0; chunk < NCHUNK; chunk++) {
            const int buf = (NBUF == 2) ? (chunk & 1) : 0;
            if (NBUF == 2 && chunk + 1 < NCHUNK) {
                uint32_t nb = sb + ((chunk + 1) & 1) * CHUNKB;
                issue_a_async(chunk + 1, nb);
                issue_b(chunk + 1, nb);
                asm volatile("cp.async.commit_group;" ::: "memory");
                asm volatile("cp.async.wait_group 1;" ::: "memory");
            } else {
                asm volatile("cp.async.wait_group 0;" ::: "memory");
            }
            __syncthreads();
            do_mma(sb + buf * CHUNKB);
            __syncthreads();
            if (NBUF == 1 && chunk + 1 < NCHUNK) {
                issue_a_async(chunk + 1, sb);
                issue_b(chunk + 1, sb);
                asm volatile("cp.async.commit_group;" ::: "memory");
            }
        }
    }

    // ---- epilogue ----
    float* yt = (float*)sm;
    const int qr = lane >> 2, qc = (lane & 3) * 2;
    #pragma unroll
    for (int nf = 0; nf < NFRAG; nf++) {
        const int coln = wn * (NT / 2) + nf * 8 + qc;
        float s0 = 0.0f, s1 = 0.0f, q0 = 0.0f, q1 = 0.0f;
        #pragma unroll
        for (int mf = 0; mf < 2; mf++) {
            float c0 = acc[mf][nf][0], c1 = acc[mf][nf][1];
            float c2 = acc[mf][nf][2], c3 = acc[mf][nf][3];
            int row = wm * 32 + mf * 16 + qr;
            if (WRITE_Y) {
                *(float2*)&Yout[(size_t)(m0 + row) * COUT + n0 + coln]     = make_float2(c0, c1);
                *(float2*)&Yout[(size_t)(m0 + row + 8) * COUT + n0 + coln] = make_float2(c2, c3);
            }
            if (DO_MAX) {
                *(float2*)&yt[row * LDT + coln]       = make_float2(c0, c1);
                *(float2*)&yt[(row + 8) * LDT + coln] = make_float2(c2, c3);
            }
            s0 += c0 + c2;  s1 += c1 + c3;
            q0 += c0 * c0 + c2 * c2;
            q1 += c1 * c1 + c3 * c3;
        }
        #pragma unroll
        for (int off = 16; off >= 4; off >>= 1) {
            s0 += __shfl_down_sync(0xffffffffu, s0, off);
            s1 += __shfl_down_sync(0xffffffffu, s1, off);
            q0 += __shfl_down_sync(0xffffffffu, q0, off);
            q1 += __shfl_down_sync(0xffffffffu, q1, off);
        }
        if (lane < 4) {
            atomicAdd(&ssumf[coln],     s0);
            atomicAdd(&ssumf[coln + 1], s1);
            atomicAdd(&ssqf [coln],     q0);
            atomicAdd(&ssqf [coln + 1], q1);
        }
    }

    if (DO_MAX) {
        __syncthreads();
        const int pbase = m0 / KNN_;
        for (int item = tid; item < 8 * NT; item += 256) {
            int s  = item / NT;
            int ch = item - s * NT;
            int p  = pbase + s;
            int rs = p * KNN_ - m0;
            int re = rs + KNN_;
            rs = rs < 0 ? 0 : rs;
            re = re > 128 ? 128 : re;
            if (rs < re) {
                float mx = yt[rs * LDT + ch];
                for (int r = rs + 1; r < re; r++) mx = fmaxf(mx, yt[r * LDT + ch]);
                atomicMax(&g_ymax[(size_t)p * 512 + chanoff + n0 + ch], enc_f(mx));
            }
        }
    }

    __syncthreads();
    for (int j = tid; j < NT; j += 256) {
        atomicAdd(&g_sum[soff + n0 + j], ssumf[j]);
        atomicAdd(&g_sq [soff + n0 + j], ssqf[j]);
    }
}

template<int CIN, bool CONVA>
constexpr int conv_smem_size() {
    return ((!CONVA && CIN / 64 >= 4) ? 2 : 1) * (2 * 128 + 2 * 64) * 128
           + 8 * 64 + (CONVA ? 8 * CIN : 0);
}

// ---------------------------------------------------------------------------
__global__ void finalize14_kernel(
    const float* __restrict__ g1, const float* __restrict__ b1,
    const float* __restrict__ g2, const float* __restrict__ b2,
    const float* __restrict__ g3, const float* __restrict__ b3,
    const float* __restrict__ g4, const float* __restrict__ b4)
{
    int o = blockIdx.x * 256 + threadIdx.x;
    if (o >= 512) return;
    const float* g; const float* bb; int loc;
    if      (o < 64)  { g = g1; bb = b1; loc = o; }
    else if (o < 128) { g = g2; bb = b2; loc = o - 64; }
    else if (o < 256) { g = g3; bb = b3; loc = o - 128; }
    else              { g = g4; bb = b4; loc = o - 256; }
    double mu  = (double)g_sum[o] / (double)M1_;
    double var = (double)g_sq [o] / (double)M1_ - mu * mu;
    var = var > 0.0 ? var : 0.0;
    float sc = g[loc] * (float)(1.0 / sqrt(var + 1e-5));
    g_scale[o] = sc;
    g_bias [o] = bb[loc] - (float)mu * sc;
}

__global__ void finalize5_kernel(const float* __restrict__ g5,
                                 const float* __restrict__ b5)
{
    int o = blockIdx.x * 256 + threadIdx.x;
    if (o >= 1024) return;
    double mu  = (double)g_sum[512 + o] / (double)ROWS_;
    double var = (double)g_sq [512 + o] / (double)ROWS_ - mu * mu;
    var = var > 0.0 ? var : 0.0;
    float sc = g5[o] * (float)(1.0 / sqrt(var + 1e-5));
    g_scale[512 + o] = sc;
    g_bias [512 + o] = b5[o] - (float)mu * sc;
}

// ---------------------------------------------------------------------------
__global__ void __launch_bounds__(256)
apply_max_all_kernel()
{
    int t = blockIdx.x * blockDim.x + threadIdx.x;
    int o = (t & 255) * 2;
    int r = t >> 8;
    float sc0 = g_scale[o],     bi0 = g_bias[o];
    float sc1 = g_scale[o + 1], bi1 = g_bias[o + 1];
    uint2 e = *(const uint2*)&g_ymax[(size_t)r * 512 + o];
    float v0 = dec_f(e.x) * sc0 + bi0; v0 = (v0 >= 0.0f) ? v0 : 0.2f * v0;
    float v1 = dec_f(e.y) * sc1 + bi1; v1 = (v1 >= 0.0f) ? v1 : 0.2f * v1;
    size_t cidx = (size_t)r * 512 + o;
    uint32_t lo;
    uint32_t hi = pack_bf2(v0, v1, lo);
    *(uint32_t*)&g_cathi[cidx] = hi;
    *(uint32_t*)&g_catlo[cidx] = lo;
}

// ---------------------------------------------------------------------------
__global__ void __launch_bounds__(256)
apply5_kernel(float* __restrict__ out)
{
    __shared__ float tile[32][33];
    const int b  = blockIdx.z;
    const int o0 = blockIdx.x * 32;
    const int n0 = blockIdx.y * 32;
    const int txx = threadIdx.x, tyy = threadIdx.y;

    float sc = g_scale[512 + o0 + txx], bi = g_bias[512 + o0 + txx];
    #pragma unroll
    for (int i = 0; i < 4; i++) {
        int n = n0 + tyy + i * 8;
        float v = g_y5[((size_t)(b * N_ + n)) * 1024 + o0 + txx];
        v = v * sc + bi;
        v = (v >= 0.0f) ? v : 0.2f * v;
        tile[tyy + i * 8][txx] = v;
    }
    __syncthreads();
    #pragma unroll
    for (int i = 0; i < 4; i++) {
        int o = o0 + tyy + i * 8;
        out[((size_t)(b * 1024 + o)) * N_ + n0 + txx] = tile[txx][tyy + i * 8];
    }
}

// ---------------------------------------------------------------------------
extern "C" void kernel_launch(void* const* d_in, const int* in_sizes, int n_in,
                              void* d_out, int out_size)
{
    const float* x  = (const float*)d_in[0];
    const float* W1 = (const float*)d_in[1];
    const float* g1 = (const float*)d_in[2];
    const float* b1 = (const float*)d_in[3];
    const float* W2 = (const float*)d_in[4];
    const float* g2 = (const float*)d_in[5];
    const float* b2 = (const float*)d_in[6];
    const float* W3 = (const float*)d_in[7];
    const float* g3 = (const float*)d_in[8];
    const float* b3 = (const float*)d_in[9];
    const float* W4 = (const float*)d_in[10];
    const float* g4 = (const float*)d_in[11];
    const float* b4 = (const float*)d_in[12];
    const float* W5 = (const float*)d_in[13];
    const float* g5 = (const float*)d_in[14];
    const float* b5 = (const float*)d_in[15];
    float* out = (float*)d_out;

    void *p_ya, *p_yb, *p_y5, *p_chi, *p_clo, *p_whi, *p_wlo;
    cudaGetSymbolAddress(&p_ya,  g_ya);
    cudaGetSymbolAddress(&p_yb,  g_yb);
    cudaGetSymbolAddress(&p_y5,  g_y5);
    cudaGetSymbolAddress(&p_chi, g_cathi);
    cudaGetSymbolAddress(&p_clo, g_catlo);
    cudaGetSymbolAddress(&p_whi, g_whi);
    cudaGetSymbolAddress(&p_wlo, g_wlo);
    float* f_ya = (float*)p_ya;
    float* f_yb = (float*)p_yb;
    float* f_y5 = (float*)p_y5;
    const __nv_bfloat16* f_chi = (const __nv_bfloat16*)p_chi;
    const __nv_bfloat16* f_clo = (const __nv_bfloat16*)p_clo;
    const __nv_bfloat16* f_whi = (const __nv_bfloat16*)p_whi;
    const __nv_bfloat16* f_wlo = (const __nv_bfloat16*)p_wlo;

    cudaFuncSetAttribute(knn_conv1_kernel, cudaFuncAttributeMaxDynamicSharedMemorySize, 92160);
    cudaFuncSetAttribute((conv_mma_kernel<64, true, true, true, 4>),
                         cudaFuncAttributeMaxDynamicSharedMemorySize, conv_smem_size<64, true>());
    cudaFuncSetAttribute((conv_mma_kernel<128, true, false, true, 3>),
                         cudaFuncAttributeMaxDynamicSharedMemorySize, conv_smem_size<128, true>());
    cudaFuncSetAttribute((conv_mma_kernel<512, false, true, false, 3>),
                         cudaFuncAttributeMaxDynamicSharedMemorySize, conv_smem_size<512, false>());

    const int MB = M1_ / 128;   // 2560

    // 0: zero BN stats
    init_stats_kernel<<<6, 256>>>();

    // 1: knn + conv1 + stats1 + ymax1 + W split + ymax init
    knn_conv1_kernel<<<dim3(N_ / 8, B_), 256, 92160>>>(x, W1, W2, W3, W4, W5);

    // 2: stage 2 (64 -> 64)  [MINB=4: measured faster on this instantiation]
    conv_mma_kernel<64, true, true, true, 4>
        <<<dim3(1, MB), 256, conv_smem_size<64, true>()>>>(
        f_ya, nullptr, nullptr, f_whi + W2_OFF, f_wlo + W2_OFF, f_yb,
        g1, b1, 64, 64, 0, 64);

    // 3: stage 3 (64 -> 128)  [MINB=4]   <-- ncu capture slot
    conv_mma_kernel<64, true, true, true, 4>
        <<<dim3(2, MB), 256, conv_smem_size<64, true>()>>>(
        f_yb, nullptr, nullptr, f_whi + W3_OFF, f_wlo + W3_OFF, f_ya,
        g2, b2, 128, 128, 64, 128);

    // 4: stage 4 (128 -> 256, max only)  [MINB=3: R13 config]
    conv_mma_kernel<128, true, false, true, 3>
        <<<dim3(4, MB), 256, conv_smem_size<128, true>()>>>(
        f_ya, nullptr, nullptr, f_whi + W4_OFF, f_wlo + W4_OFF, nullptr,
        g3, b3, 256, 256, 128, 256);

    // 5-6: finalize stages 1-4 + single cat pass
    finalize14_kernel<<<2, 256>>>(g1, b1, g2, b2, g3, b3, g4, b4);
    apply_max_all_kernel<<<(ROWS_ * 256) / 256, 256>>>();

    // 7: stage 5 (512 -> 1024)  [MINB=3: R13 config]
    conv_mma_kernel<512, false, true, false, 3>
        <<<dim3(16, ROWS_ / 128), 256, conv_smem_size<512, false>()>>>(
        nullptr, f_chi, f_clo, f_whi + W5_OFF, f_wlo + W5_OFF, f_y5,
        nullptr, nullptr, 1024, 512, 0, 0);
    finalize5_kernel<<<4, 256>>>(g5, b5);
    apply5_kernel<<<dim3(32, 64, B_), dim3(32, 8)>>>(out);

    (void)in_sizes; (void)n_in; (void)out_size;
}